// round 3
// baseline (speedup 1.0000x reference)
#include <cuda_runtime.h>
#include <cuda_bf16.h>

// ---------------- problem constants ----------------
#define BB   4
#define TT   16
#define NN   1000
#define FIN  8
#define EE   8000
#define EP   9000          // edges + self loops
#define HID  64
#define HEADS 4
#define LL   5
#define GG   64            // B*T graphs
#define RR   64000         // G*N rows
#define NH   64000         // N*HID
#define GATES 192
#define KCH  512
#define NCHUNK 125

// ---------------- device scratch ----------------
__device__ float g_X0[RR * HID];
__device__ float g_X1[RR * HID];
__device__ float g_H [RR * HEADS * HID];
__device__ float g_ls[RR * HEADS];
__device__ float g_ld[RR * HEADS];
__device__ int   g_off[NN + 1];
__device__ int   g_srcList[EP];
__device__ int   g_eid[EP];
__device__ float g_GIpart[NCHUNK * GG * GATES];
__device__ float g_GI[GG * GATES];
__device__ float g_hT[BB * HID];

// ---------------- CSR build: ONE kernel, one block (deterministic) -----------
__global__ void __launch_bounds__(1024) k_csr_all(const int* __restrict__ edge_index) {
    __shared__ int scnt[1024];
    __shared__ int sscan[1024];
    __shared__ int scur[1024];
    int tid = threadIdx.x;
    scnt[tid] = 0;
    __syncthreads();
    for (int e = tid; e < EE; e += 1024)
        atomicAdd(&scnt[edge_index[EE + e]], 1);
    __syncthreads();
    int v = (tid < NN) ? (scnt[tid] + 1) : 0;    // +1 self loop
    sscan[tid] = v;
    __syncthreads();
    for (int o = 1; o < 1024; o <<= 1) {
        int add = (tid >= o) ? sscan[tid - o] : 0;
        __syncthreads();
        sscan[tid] += add;
        __syncthreads();
    }
    if (tid < NN) {
        g_off[tid + 1] = sscan[tid];
        scur[tid] = (tid == 0) ? 0 : sscan[tid - 1];
    }
    if (tid == 0) g_off[0] = 0;
    __syncthreads();
    for (int e = tid; e < EP; e += 1024) {
        int s, d;
        if (e < EE) { s = edge_index[e]; d = edge_index[EE + e]; }
        else        { s = e - EE;        d = e - EE; }
        int pos = atomicAdd(&scur[d], 1);
        g_srcList[pos] = s;
        g_eid[pos] = e;
    }
    __syncthreads();
    if (tid < NN) {                       // stable order by edge id
        int s0 = g_off[tid], s1 = g_off[tid + 1];
        for (int i = s0 + 1; i < s1; i++) {
            int id = g_eid[i], sv = g_srcList[i];
            int j = i - 1;
            while (j >= s0 && g_eid[j] > id) {
                g_eid[j + 1] = g_eid[j];
                g_srcList[j + 1] = g_srcList[j];
                j--;
            }
            g_eid[j + 1] = id;
            g_srcList[j + 1] = sv;
        }
    }
}

// ---------------- input projection ----------------
__global__ void k_input_fc(const float* __restrict__ x,
                           const float* __restrict__ W_in,
                           const float* __restrict__ b_in) {
    int tid = threadIdx.x;
    int r = blockIdx.x * 4 + (tid >> 6);
    int c = tid & 63;
    float s = b_in[c];
#pragma unroll
    for (int f = 0; f < FIN; f++)
        s += x[r * FIN + f] * W_in[f * HID + c];
    g_X0[r * HID + c] = s;
}

// ---------------- GAT GEMM + fused ls/ld epilogue -----------------------------
// H = X @ Wg[l] ([64000,64]x[64,256]); tile M=64, N=256(full), K in 2 halves.
// Epilogue: ls[r][h] = H[r]·a_src[h], ld likewise, via 64x4x16 smem reduction.
__global__ void __launch_bounds__(256) k_gat_gemm(int inBuf, const float* __restrict__ W,
                                                  const float* __restrict__ asrc,
                                                  const float* __restrict__ adst) {
    __shared__ float sm[12288];                 // 48KB, aliased
    float (*As)[64]  = (float(*)[64])sm;        // [64][64]
    float (*Ws)[256] = (float(*)[256])(sm + 4096); // [32][256]
    const float* __restrict__ X = inBuf ? g_X1 : g_X0;
    int rowBase = blockIdx.x * 64;
    int tid = threadIdx.x;

    const float4* X4 = (const float4*)(X + (size_t)rowBase * 64);
#pragma unroll
    for (int q = 0; q < 4; q++) {
        int idx = tid + q * 256;
        int r = idx & 63, k4 = idx >> 6;
        float4 v = X4[r * 16 + k4];
        As[k4 * 4 + 0][r] = v.x;
        As[k4 * 4 + 1][r] = v.y;
        As[k4 * 4 + 2][r] = v.z;
        As[k4 * 4 + 3][r] = v.w;
    }

    int lane = tid & 31, w = tid >> 5;
    int ry2 = lane >> 2, cx2 = lane & 3;
    int cg = w * 4 + cx2;                       // 0..31
    float acc[8][8] = {};
    const float4* W4 = (const float4*)W;

#pragma unroll
    for (int half = 0; half < 2; half++) {
        __syncthreads();
#pragma unroll
        for (int q = 0; q < 8; q++) {
            int idx = tid + q * 256;
            ((float4*)Ws)[idx] = W4[half * 2048 + idx];
        }
        __syncthreads();
#pragma unroll
        for (int kk = 0; kk < 32; kk++) {
            int k = half * 32 + kk;
            float4 a0 = *(const float4*)&As[k][ry2 * 4];
            float4 a1 = *(const float4*)&As[k][32 + ry2 * 4];
            float4 b0 = *(const float4*)&Ws[kk][cg * 4];
            float4 b1 = *(const float4*)&Ws[kk][128 + cg * 4];
            float av[8] = {a0.x, a0.y, a0.z, a0.w, a1.x, a1.y, a1.z, a1.w};
            float bv[8] = {b0.x, b0.y, b0.z, b0.w, b1.x, b1.y, b1.z, b1.w};
#pragma unroll
            for (int i = 0; i < 8; i++)
#pragma unroll
                for (int j = 0; j < 8; j++)
                    acc[i][j] += av[i] * bv[j];
        }
    }
    // store H
#pragma unroll
    for (int i = 0; i < 8; i++) {
        int r = rowBase + ((i < 4) ? (ry2 * 4 + i) : (32 + ry2 * 4 + (i - 4)));
        *(float4*)&g_H[(size_t)r * 256 + cg * 4] =
            make_float4(acc[i][0], acc[i][1], acc[i][2], acc[i][3]);
        *(float4*)&g_H[(size_t)r * 256 + 128 + cg * 4] =
            make_float4(acc[i][4], acc[i][5], acc[i][6], acc[i][7]);
    }

    // ---- fused ls/ld epilogue ----
    __syncthreads();                            // done reading As/Ws
    float (*redls)[4][16] = (float(*)[4][16])sm;          // [64][4][16]
    float (*redld)[4][16] = (float(*)[4][16])(sm + 4096);
    float as_lo[4], as_hi[4], ad_lo[4], ad_hi[4];
#pragma unroll
    for (int j = 0; j < 4; j++) {
        as_lo[j] = asrc[cg * 4 + j];
        as_hi[j] = asrc[128 + cg * 4 + j];
        ad_lo[j] = adst[cg * 4 + j];
        ad_hi[j] = adst[128 + cg * 4 + j];
    }
    int hA = cg >> 4;                           // head of low half (0/1)
    int slot = (w & 3) * 4 + cx2;               // 0..15
#pragma unroll
    for (int i = 0; i < 8; i++) {
        int r = (i < 4) ? (ry2 * 4 + i) : (32 + ry2 * 4 + (i - 4));
        float pls0 = 0, pls1 = 0, pld0 = 0, pld1 = 0;
#pragma unroll
        for (int j = 0; j < 4; j++) {
            pls0 += acc[i][j] * as_lo[j];
            pls1 += acc[i][4 + j] * as_hi[j];
            pld0 += acc[i][j] * ad_lo[j];
            pld1 += acc[i][4 + j] * ad_hi[j];
        }
        redls[r][hA][slot] = pls0;
        redls[r][2 + hA][slot] = pls1;
        redld[r][hA][slot] = pld0;
        redld[r][2 + hA][slot] = pld1;
    }
    __syncthreads();
    {
        int r = tid >> 2, h = tid & 3;
        float s = 0, d = 0;
#pragma unroll
        for (int k = 0; k < 16; k++) { s += redls[r][h][k]; d += redld[r][h][k]; }
        g_ls[(rowBase + r) * 4 + h] = s;
        g_ld[(rowBase + r) * 4 + h] = d;
    }
}

// ---------------- GAT aggregate: smem-resident H slice ------------------------
// Block = (graph g, hc) ; hc -> head h = hc>>1, half = hc&1 (32 channels).
// Loads H slice [1000][32] to smem, per-node softmax in registers, in-place out.
__global__ void __launch_bounds__(256) k_gat_agg2() {
    extern __shared__ float Hs[];               // [1000][32] = 128000 B
    int g = blockIdx.x, hc = blockIdx.y;
    int h = hc >> 1, half = hc & 1;
    int tid = threadIdx.x, lane = tid & 31, w = tid >> 5;
    size_t gb = (size_t)g * NN;
    int colBase = h * 64 + half * 32;

    // phase A: load slice
    for (int idx = tid; idx < NN * 8; idx += 256) {
        int n = idx >> 3, c4 = idx & 7;
        ((float4*)Hs)[idx] = *(const float4*)&g_H[(gb + n) * 256 + colBase + c4 * 4];
    }
    __syncthreads();

    // phase B+C per node (warp-per-node)
    for (int n = w; n < NN; n += 8) {
        int s0 = g_off[n];
        int deg = g_off[n + 1] - s0;
        float ldv = g_ld[(gb + n) * 4 + h];
        float lsum = 0.f;
        int s_c = 0; float w_c = 0.f;
        for (int base = 0; base < deg; base += 32) {
            int e = base + lane;
            int s = 0; float wv = 0.f;
            if (e < deg) {
                s = g_srcList[s0 + e];
                float v = g_ls[(gb + s) * 4 + h] + ldv;
                v = v > 0.f ? v : 0.2f * v;
                wv = __expf(v);
            }
            if (base == 0) { s_c = s; w_c = wv; }
            lsum += wv;
        }
#pragma unroll
        for (int o = 16; o > 0; o >>= 1)
            lsum += __shfl_xor_sync(0xffffffffu, lsum, o);
        float inv = 1.f / (lsum + 1e-16f);

        float acc = 0.f;
        for (int base = 0; base < deg; base += 32) {
            int s; float wv;
            if (base == 0) { s = s_c; wv = w_c; }
            else {
                int e = base + lane;
                s = 0; wv = 0.f;
                if (e < deg) {
                    s = g_srcList[s0 + e];
                    float v = g_ls[(gb + s) * 4 + h] + ldv;
                    v = v > 0.f ? v : 0.2f * v;
                    wv = __expf(v);
                }
            }
            int cnt = min(32, deg - base);
#pragma unroll 4
            for (int j = 0; j < cnt; j++) {
                int si = __shfl_sync(0xffffffffu, s, j);
                float wj = __shfl_sync(0xffffffffu, wv, j);
                acc += wj * Hs[si * 32 + lane];
            }
        }
        acc *= inv;
        g_H[(gb + n) * 256 + colBase + lane] = acc;   // in-place (slice private)
    }
}

// ---------------- head mean + bias + elu -> X ----------------
__global__ void k_finish(const float* __restrict__ bg_l, int outBuf) {
    float* __restrict__ Xout = outBuf ? g_X1 : g_X0;
    int tid = threadIdx.x;
    int r = blockIdx.x * 4 + (tid >> 6);
    int c = tid & 63;
    const float* Hr = &g_H[(size_t)r * 256];
    float v = 0.25f * ((Hr[c] + Hr[64 + c]) + (Hr[128 + c] + Hr[192 + c])) + bg_l[c];
    v = v > 0.f ? v : expm1f(v);
    Xout[(size_t)r * 64 + c] = v;
}

// ---------------- GI split-K GEMM -------------------------------------------
__global__ void __launch_bounds__(256) k_gi_gemm(const float* __restrict__ Wih) {
    __shared__ float As[64][33];
    __shared__ float Ws[64][33];
    int kBase = blockIdx.x * KCH;
    int gateBase = blockIdx.y * 64;
    int tid = threadIdx.x;
    int tx = tid & 15, ty = tid >> 4;
    float acc[4][4] = {};
    for (int kt = 0; kt < KCH / 32; kt++) {
        int k0 = kBase + kt * 32;
#pragma unroll
        for (int i = 0; i < 8; i++) {
            int idx = tid + i * 256;
            int r = idx >> 5, kk = idx & 31;
            As[r][kk] = g_X1[r * NH + k0 + kk];
            Ws[r][kk] = Wih[(size_t)(gateBase + r) * NH + k0 + kk];
        }
        __syncthreads();
#pragma unroll
        for (int kk = 0; kk < 32; kk++) {
            float a[4], wv[4];
#pragma unroll
            for (int i = 0; i < 4; i++) a[i] = As[ty * 4 + i][kk];
#pragma unroll
            for (int j = 0; j < 4; j++) wv[j] = Ws[tx * 4 + j][kk];
#pragma unroll
            for (int i = 0; i < 4; i++)
#pragma unroll
                for (int j = 0; j < 4; j++)
                    acc[i][j] += a[i] * wv[j];
        }
        __syncthreads();
    }
#pragma unroll
    for (int i = 0; i < 4; i++)
#pragma unroll
        for (int j = 0; j < 4; j++)
            g_GIpart[(blockIdx.x * GG + ty * 4 + i) * GATES + gateBase + tx * 4 + j] = acc[i][j];
}

__global__ void k_gi_reduce(const float* __restrict__ b_ih) {
    int idx = blockIdx.x * blockDim.x + threadIdx.x;
    int j = idx % GATES;
    float s = b_ih[j];
    for (int kc = 0; kc < NCHUNK; kc++)
        s += g_GIpart[kc * GG * GATES + idx];
    g_GI[idx] = s;
}

// ---------------- GRU recurrence ----------------
__global__ void __launch_bounds__(256) k_gru(const float* __restrict__ Whh,
                                             const float* __restrict__ bhh) {
    __shared__ float h[BB][HID];
    __shared__ float gh[BB][GATES];
    int tid = threadIdx.x;
    h[tid >> 6][tid & 63] = 0.f;
    __syncthreads();
    for (int t = 0; t < TT; t++) {
#pragma unroll
        for (int q = 0; q < 3; q++) {
            int idx = tid + q * 256;
            int b = idx / GATES, j = idx % GATES;
            float s = bhh[j];
#pragma unroll
            for (int c = 0; c < HID; c++)
                s += h[b][c] * Whh[j * HID + c];
            gh[b][j] = s;
        }
        __syncthreads();
        int b = tid >> 6, c = tid & 63;
        int g = b * TT + t;
        float ir = g_GI[g * GATES + c]        + gh[b][c];
        float iz = g_GI[g * GATES + 64 + c]   + gh[b][64 + c];
        float in = g_GI[g * GATES + 128 + c];
        float hn = gh[b][128 + c];
        float r = 1.f / (1.f + expf(-ir));
        float z = 1.f / (1.f + expf(-iz));
        float nn = tanhf(in + r * hn);
        float hnew = (1.f - z) * nn + z * h[b][c];
        __syncthreads();
        h[b][c] = hnew;
        __syncthreads();
    }
    g_hT[tid] = h[tid >> 6][tid & 63];
}

// ---------------- final FC ----------------
__global__ void k_fc(const float* __restrict__ Wfc, const float* __restrict__ bfc,
                     float* __restrict__ out) {
    int b = blockIdx.x;
    int n = blockIdx.y * 256 + threadIdx.x;
    if (n >= NN) return;
    float s = bfc[n];
#pragma unroll
    for (int c = 0; c < HID; c++)
        s += g_hT[b * HID + c] * Wfc[c * NN + n];
    out[b * NN + n] = s;
}

// ---------------- launcher ----------------
extern "C" void kernel_launch(void* const* d_in, const int* in_sizes, int n_in,
                              void* d_out, int out_size) {
    const float* x_seq = (const float*)d_in[0];
    const int*   edge_index = (const int*)d_in[1];
    const float* W_in = (const float*)d_in[3];
    const float* b_in = (const float*)d_in[4];
    const float* Wg   = (const float*)d_in[5];
    const float* a_src= (const float*)d_in[6];
    const float* a_dst= (const float*)d_in[7];
    const float* bg   = (const float*)d_in[8];
    const float* W_ih = (const float*)d_in[9];
    const float* W_hh = (const float*)d_in[10];
    const float* b_ih = (const float*)d_in[11];
    const float* b_hh = (const float*)d_in[12];
    const float* W_fc = (const float*)d_in[13];
    const float* b_fc = (const float*)d_in[14];
    float* out = (float*)d_out;

    static int smemSet = 0;
    if (!smemSet) {
        cudaFuncSetAttribute(k_gat_agg2,
                             cudaFuncAttributeMaxDynamicSharedMemorySize, 131072);
        smemSet = 1;
    }

    // 1: CSR build, 2: input proj
    k_csr_all<<<1, 1024>>>(edge_index);
    k_input_fc<<<RR / 4, 256>>>(x_seq, W_in, b_in);

    // 5 GAT layers: gemm(+lsld), agg (launch #4 overall = layer0 agg), finish
    for (int l = 0; l < LL; l++) {
        int inBuf = l & 1;
        int outBuf = 1 - inBuf;
        k_gat_gemm<<<RR / 64, 256>>>(inBuf, Wg + (size_t)l * HID * 256,
                                     a_src + (size_t)l * HEADS * HID,
                                     a_dst + (size_t)l * HEADS * HID);
        k_gat_agg2<<<dim3(GG, 8), 256, 128000>>>();
        k_finish<<<RR / 4, 256>>>(bg + (size_t)l * HID, outBuf);
    }
    // final features in g_X1

    k_gi_gemm<<<dim3(NCHUNK, 3), 256>>>(W_ih);
    k_gi_reduce<<<(GG * GATES) / 256, 256>>>(b_ih);
    k_gru<<<1, 256>>>(W_hh, b_hh);
    k_fc<<<dim3(BB, 4), 256>>>(W_fc, b_fc, out);
}

// round 4
// speedup vs baseline: 2.3217x; 2.3217x over previous
#include <cuda_runtime.h>
#include <cuda_bf16.h>

// ---------------- problem constants ----------------
#define BB   4
#define TT   16
#define NN   1000
#define FIN  8
#define EE   8000
#define EP   9000          // edges + self loops
#define HID  64
#define HEADS 4
#define LL   5
#define GG   64            // B*T graphs
#define RR   64000         // G*N rows
#define NH   64000         // N*HID
#define GATES 192
#define KCH  512
#define NCHUNK 125

#define AGG_SMEM ((32000 + 2*EP + 3*NN) * 4)   // 212000 bytes

// ---------------- device scratch ----------------
__device__ float g_X0[RR * HID];
__device__ float g_X1[RR * HID];
__device__ float g_H [RR * HEADS * HID];
__device__ float g_ls[RR * HEADS];
__device__ float g_ld[RR * HEADS];
__device__ int   g_off[NN + 1];
__device__ int   g_srcList[EP];
__device__ int   g_eid[EP];
__device__ float g_GIpart[NCHUNK * GG * GATES];
__device__ float g_GI[GG * GATES];
__device__ float g_hT[BB * HID];

// ---------------- CSR build: ONE kernel, one block (deterministic) -----------
__global__ void __launch_bounds__(1024) k_csr_all(const int* __restrict__ edge_index) {
    __shared__ int scnt[1024];
    __shared__ int sscan[1024];
    __shared__ int scur[1024];
    int tid = threadIdx.x;
    scnt[tid] = 0;
    __syncthreads();
    for (int e = tid; e < EE; e += 1024)
        atomicAdd(&scnt[edge_index[EE + e]], 1);
    __syncthreads();
    int v = (tid < NN) ? (scnt[tid] + 1) : 0;    // +1 self loop
    sscan[tid] = v;
    __syncthreads();
    for (int o = 1; o < 1024; o <<= 1) {
        int add = (tid >= o) ? sscan[tid - o] : 0;
        __syncthreads();
        sscan[tid] += add;
        __syncthreads();
    }
    if (tid < NN) {
        g_off[tid + 1] = sscan[tid];
        scur[tid] = (tid == 0) ? 0 : sscan[tid - 1];
    }
    if (tid == 0) g_off[0] = 0;
    __syncthreads();
    for (int e = tid; e < EP; e += 1024) {
        int s, d;
        if (e < EE) { s = edge_index[e]; d = edge_index[EE + e]; }
        else        { s = e - EE;        d = e - EE; }
        int pos = atomicAdd(&scur[d], 1);
        g_srcList[pos] = s;
        g_eid[pos] = e;
    }
    __syncthreads();
    if (tid < NN) {                       // stable order by edge id
        int s0 = g_off[tid], s1 = g_off[tid + 1];
        for (int i = s0 + 1; i < s1; i++) {
            int id = g_eid[i], sv = g_srcList[i];
            int j = i - 1;
            while (j >= s0 && g_eid[j] > id) {
                g_eid[j + 1] = g_eid[j];
                g_srcList[j + 1] = g_srcList[j];
                j--;
            }
            g_eid[j + 1] = id;
            g_srcList[j + 1] = sv;
        }
    }
}

// ---------------- input projection ----------------
__global__ void k_input_fc(const float* __restrict__ x,
                           const float* __restrict__ W_in,
                           const float* __restrict__ b_in) {
    int tid = threadIdx.x;
    int r = blockIdx.x * 4 + (tid >> 6);
    int c = tid & 63;
    float s = b_in[c];
#pragma unroll
    for (int f = 0; f < FIN; f++)
        s += x[r * FIN + f] * W_in[f * HID + c];
    g_X0[r * HID + c] = s;
}

// ---------------- GAT GEMM + fused ls/ld epilogue -----------------------------
__global__ void __launch_bounds__(256) k_gat_gemm(int inBuf, const float* __restrict__ W,
                                                  const float* __restrict__ asrc,
                                                  const float* __restrict__ adst) {
    __shared__ float sm[12288];                 // 48KB, aliased
    float (*As)[64]  = (float(*)[64])sm;        // [64][64]
    float (*Ws)[256] = (float(*)[256])(sm + 4096); // [32][256]
    const float* __restrict__ X = inBuf ? g_X1 : g_X0;
    int rowBase = blockIdx.x * 64;
    int tid = threadIdx.x;

    const float4* X4 = (const float4*)(X + (size_t)rowBase * 64);
#pragma unroll
    for (int q = 0; q < 4; q++) {
        int idx = tid + q * 256;
        int r = idx & 63, k4 = idx >> 6;
        float4 v = X4[r * 16 + k4];
        As[k4 * 4 + 0][r] = v.x;
        As[k4 * 4 + 1][r] = v.y;
        As[k4 * 4 + 2][r] = v.z;
        As[k4 * 4 + 3][r] = v.w;
    }

    int lane = tid & 31, w = tid >> 5;
    int ry2 = lane >> 2, cx2 = lane & 3;
    int cg = w * 4 + cx2;                       // 0..31
    float acc[8][8] = {};
    const float4* W4 = (const float4*)W;

#pragma unroll
    for (int half = 0; half < 2; half++) {
        __syncthreads();
#pragma unroll
        for (int q = 0; q < 8; q++) {
            int idx = tid + q * 256;
            ((float4*)Ws)[idx] = W4[half * 2048 + idx];
        }
        __syncthreads();
#pragma unroll
        for (int kk = 0; kk < 32; kk++) {
            int k = half * 32 + kk;
            float4 a0 = *(const float4*)&As[k][ry2 * 4];
            float4 a1 = *(const float4*)&As[k][32 + ry2 * 4];
            float4 b0 = *(const float4*)&Ws[kk][cg * 4];
            float4 b1 = *(const float4*)&Ws[kk][128 + cg * 4];
            float av[8] = {a0.x, a0.y, a0.z, a0.w, a1.x, a1.y, a1.z, a1.w};
            float bv[8] = {b0.x, b0.y, b0.z, b0.w, b1.x, b1.y, b1.z, b1.w};
#pragma unroll
            for (int i = 0; i < 8; i++)
#pragma unroll
                for (int j = 0; j < 8; j++)
                    acc[i][j] += av[i] * bv[j];
        }
    }
    // store H
#pragma unroll
    for (int i = 0; i < 8; i++) {
        int r = rowBase + ((i < 4) ? (ry2 * 4 + i) : (32 + ry2 * 4 + (i - 4)));
        *(float4*)&g_H[(size_t)r * 256 + cg * 4] =
            make_float4(acc[i][0], acc[i][1], acc[i][2], acc[i][3]);
        *(float4*)&g_H[(size_t)r * 256 + 128 + cg * 4] =
            make_float4(acc[i][4], acc[i][5], acc[i][6], acc[i][7]);
    }

    // ---- fused ls/ld epilogue ----
    __syncthreads();                            // done reading As/Ws
    float (*redls)[4][16] = (float(*)[4][16])sm;          // [64][4][16]
    float (*redld)[4][16] = (float(*)[4][16])(sm + 4096);
    float as_lo[4], as_hi[4], ad_lo[4], ad_hi[4];
#pragma unroll
    for (int j = 0; j < 4; j++) {
        as_lo[j] = asrc[cg * 4 + j];
        as_hi[j] = asrc[128 + cg * 4 + j];
        ad_lo[j] = adst[cg * 4 + j];
        ad_hi[j] = adst[128 + cg * 4 + j];
    }
    int hA = cg >> 4;                           // head of low half (0/1)
    int slot = (w & 3) * 4 + cx2;               // 0..15
#pragma unroll
    for (int i = 0; i < 8; i++) {
        int r = (i < 4) ? (ry2 * 4 + i) : (32 + ry2 * 4 + (i - 4));
        float pls0 = 0, pls1 = 0, pld0 = 0, pld1 = 0;
#pragma unroll
        for (int j = 0; j < 4; j++) {
            pls0 += acc[i][j] * as_lo[j];
            pls1 += acc[i][4 + j] * as_hi[j];
            pld0 += acc[i][j] * ad_lo[j];
            pld1 += acc[i][4 + j] * ad_hi[j];
        }
        redls[r][hA][slot] = pls0;
        redls[r][2 + hA][slot] = pls1;
        redld[r][hA][slot] = pld0;
        redld[r][2 + hA][slot] = pld1;
    }
    __syncthreads();
    {
        int r = tid >> 2, h = tid & 3;
        float s = 0, d = 0;
#pragma unroll
        for (int k = 0; k < 16; k++) { s += redls[r][h][k]; d += redld[r][h][k]; }
        g_ls[(rowBase + r) * 4 + h] = s;
        g_ld[(rowBase + r) * 4 + h] = d;
    }
}

// ---------------- GAT aggregate v3: all-smem, no shuffles --------------------
// Block = (graph g, hc): h = hc>>1, half = hc&1 (32 channels). 512 threads.
// smem: Hs[1000][32] | sw[EP] | ssrc[EP] | sls[1000] | sld[1000] | snorm[1000]
__global__ void __launch_bounds__(512) k_gat_agg3() {
    extern __shared__ float sm[];
    float* Hs    = sm;                       // 32000 floats
    float* sw    = sm + 32000;               // EP
    int*   ssrc  = (int*)(sm + 32000 + EP);  // EP
    float* sls   = sm + 32000 + 2 * EP;      // NN
    float* sld   = sls + NN;                 // NN
    float* snorm = sld + NN;                 // NN

    int g = blockIdx.x, hc = blockIdx.y;
    int h = hc >> 1, half = hc & 1;
    int tid = threadIdx.x, lane = tid & 31, w = tid >> 5;
    size_t gb = (size_t)g * NN;
    int colBase = h * 64 + half * 32;

    // Phase A: load H slice + per-node logits
    for (int idx = tid; idx < NN * 8; idx += 512) {
        int n = idx >> 3, c4 = idx & 7;
        ((float4*)Hs)[idx] = *(const float4*)&g_H[(gb + n) * 256 + colBase + c4 * 4];
    }
    for (int n = tid; n < NN; n += 512) {
        sls[n] = g_ls[(gb + n) * 4 + h];
        sld[n] = g_ld[(gb + n) * 4 + h];
    }
    __syncthreads();

    // Phase B: thread-per-node edge weights + normalizer (smem only, no shfl)
    for (int n = tid; n < NN; n += 512) {
        int s0 = g_off[n], s1 = g_off[n + 1];
        float ldv = sld[n];
        float sum = 0.f;
        for (int j = s0; j < s1; j++) {
            int s = g_srcList[j];
            float v = sls[s] + ldv;
            v = v > 0.f ? v : 0.2f * v;
            float wv = __expf(v);
            ssrc[j] = s;
            sw[j] = wv;
            sum += wv;
        }
        snorm[n] = 1.f / (sum + 1e-16f);
    }
    __syncthreads();

    // Phase D: warp-per-node aggregate; sw/ssrc broadcast, Hs conflict-free
    for (int n = w; n < NN; n += 16) {
        int s0 = g_off[n], s1 = g_off[n + 1];
        float acc = 0.f;
        int j = s0;
        for (; j + 4 <= s1; j += 4) {
            float w0 = sw[j],     w1 = sw[j + 1], w2 = sw[j + 2], w3 = sw[j + 3];
            int   i0 = ssrc[j],   i1 = ssrc[j + 1], i2 = ssrc[j + 2], i3 = ssrc[j + 3];
            acc += w0 * Hs[i0 * 32 + lane] + w1 * Hs[i1 * 32 + lane]
                 + w2 * Hs[i2 * 32 + lane] + w3 * Hs[i3 * 32 + lane];
        }
        for (; j < s1; j++)
            acc += sw[j] * Hs[ssrc[j] * 32 + lane];
        g_H[(gb + n) * 256 + colBase + lane] = acc * snorm[n];  // in-place
    }
}

// ---------------- head mean + bias + elu -> X ----------------
__global__ void k_finish(const float* __restrict__ bg_l, int outBuf) {
    float* __restrict__ Xout = outBuf ? g_X1 : g_X0;
    int tid = threadIdx.x;
    int r = blockIdx.x * 4 + (tid >> 6);
    int c = tid & 63;
    const float* Hr = &g_H[(size_t)r * 256];
    float v = 0.25f * ((Hr[c] + Hr[64 + c]) + (Hr[128 + c] + Hr[192 + c])) + bg_l[c];
    v = v > 0.f ? v : expm1f(v);
    Xout[(size_t)r * 64 + c] = v;
}

// ---------------- GI split-K GEMM -------------------------------------------
__global__ void __launch_bounds__(256) k_gi_gemm(const float* __restrict__ Wih) {
    __shared__ float As[64][33];
    __shared__ float Ws[64][33];
    int kBase = blockIdx.x * KCH;
    int gateBase = blockIdx.y * 64;
    int tid = threadIdx.x;
    int tx = tid & 15, ty = tid >> 4;
    float acc[4][4] = {};
    for (int kt = 0; kt < KCH / 32; kt++) {
        int k0 = kBase + kt * 32;
#pragma unroll
        for (int i = 0; i < 8; i++) {
            int idx = tid + i * 256;
            int r = idx >> 5, kk = idx & 31;
            As[r][kk] = g_X1[r * NH + k0 + kk];
            Ws[r][kk] = Wih[(size_t)(gateBase + r) * NH + k0 + kk];
        }
        __syncthreads();
#pragma unroll
        for (int kk = 0; kk < 32; kk++) {
            float a[4], wv[4];
#pragma unroll
            for (int i = 0; i < 4; i++) a[i] = As[ty * 4 + i][kk];
#pragma unroll
            for (int j = 0; j < 4; j++) wv[j] = Ws[tx * 4 + j][kk];
#pragma unroll
            for (int i = 0; i < 4; i++)
#pragma unroll
                for (int j = 0; j < 4; j++)
                    acc[i][j] += a[i] * wv[j];
        }
        __syncthreads();
    }
#pragma unroll
    for (int i = 0; i < 4; i++)
#pragma unroll
        for (int j = 0; j < 4; j++)
            g_GIpart[(blockIdx.x * GG + ty * 4 + i) * GATES + gateBase + tx * 4 + j] = acc[i][j];
}

__global__ void k_gi_reduce(const float* __restrict__ b_ih) {
    int idx = blockIdx.x * blockDim.x + threadIdx.x;
    int j = idx % GATES;
    float s = b_ih[j];
    for (int kc = 0; kc < NCHUNK; kc++)
        s += g_GIpart[kc * GG * GATES + idx];
    g_GI[idx] = s;
}

// ---------------- GRU recurrence ----------------
__global__ void __launch_bounds__(256) k_gru(const float* __restrict__ Whh,
                                             const float* __restrict__ bhh) {
    __shared__ float h[BB][HID];
    __shared__ float gh[BB][GATES];
    int tid = threadIdx.x;
    h[tid >> 6][tid & 63] = 0.f;
    __syncthreads();
    for (int t = 0; t < TT; t++) {
#pragma unroll
        for (int q = 0; q < 3; q++) {
            int idx = tid + q * 256;
            int b = idx / GATES, j = idx % GATES;
            float s = bhh[j];
#pragma unroll
            for (int c = 0; c < HID; c++)
                s += h[b][c] * Whh[j * HID + c];
            gh[b][j] = s;
        }
        __syncthreads();
        int b = tid >> 6, c = tid & 63;
        int g = b * TT + t;
        float ir = g_GI[g * GATES + c]        + gh[b][c];
        float iz = g_GI[g * GATES + 64 + c]   + gh[b][64 + c];
        float in = g_GI[g * GATES + 128 + c];
        float hn = gh[b][128 + c];
        float r = 1.f / (1.f + expf(-ir));
        float z = 1.f / (1.f + expf(-iz));
        float nn = tanhf(in + r * hn);
        float hnew = (1.f - z) * nn + z * h[b][c];
        __syncthreads();
        h[b][c] = hnew;
        __syncthreads();
    }
    g_hT[tid] = h[tid >> 6][tid & 63];
}

// ---------------- final FC ----------------
__global__ void k_fc(const float* __restrict__ Wfc, const float* __restrict__ bfc,
                     float* __restrict__ out) {
    int b = blockIdx.x;
    int n = blockIdx.y * 256 + threadIdx.x;
    if (n >= NN) return;
    float s = bfc[n];
#pragma unroll
    for (int c = 0; c < HID; c++)
        s += g_hT[b * HID + c] * Wfc[c * NN + n];
    out[b * NN + n] = s;
}

// ---------------- launcher ----------------
extern "C" void kernel_launch(void* const* d_in, const int* in_sizes, int n_in,
                              void* d_out, int out_size) {
    const float* x_seq = (const float*)d_in[0];
    const int*   edge_index = (const int*)d_in[1];
    const float* W_in = (const float*)d_in[3];
    const float* b_in = (const float*)d_in[4];
    const float* Wg   = (const float*)d_in[5];
    const float* a_src= (const float*)d_in[6];
    const float* a_dst= (const float*)d_in[7];
    const float* bg   = (const float*)d_in[8];
    const float* W_ih = (const float*)d_in[9];
    const float* W_hh = (const float*)d_in[10];
    const float* b_ih = (const float*)d_in[11];
    const float* b_hh = (const float*)d_in[12];
    const float* W_fc = (const float*)d_in[13];
    const float* b_fc = (const float*)d_in[14];
    float* out = (float*)d_out;

    cudaFuncSetAttribute(k_gat_agg3,
                         cudaFuncAttributeMaxDynamicSharedMemorySize, AGG_SMEM);

    // 1: CSR build, 2: input proj
    k_csr_all<<<1, 1024>>>(edge_index);
    k_input_fc<<<RR / 4, 256>>>(x_seq, W_in, b_in);

    // 5 GAT layers: gemm(+lsld) (launch 3), agg3 (launch 4 -> ncu slot), finish
    for (int l = 0; l < LL; l++) {
        int inBuf = l & 1;
        int outBuf = 1 - inBuf;
        k_gat_gemm<<<RR / 64, 256>>>(inBuf, Wg + (size_t)l * HID * 256,
                                     a_src + (size_t)l * HEADS * HID,
                                     a_dst + (size_t)l * HEADS * HID);
        k_gat_agg3<<<dim3(GG, 8), 512, AGG_SMEM>>>();
        k_finish<<<RR / 4, 256>>>(bg + (size_t)l * HID, outBuf);
    }
    // final features in g_X1

    k_gi_gemm<<<dim3(NCHUNK, 3), 256>>>(W_ih);
    k_gi_reduce<<<(GG * GATES) / 256, 256>>>(b_ih);
    k_gru<<<1, 256>>>(W_hh, b_hh);
    k_fc<<<dim3(BB, 4), 256>>>(W_fc, b_fc, out);
}

// round 5
// speedup vs baseline: 2.3831x; 1.0264x over previous
#include <cuda_runtime.h>
#include <cuda_bf16.h>

// ---------------- problem constants ----------------
#define BB   4
#define TT   16
#define NN   1000
#define FIN  8
#define EE   8000
#define EP   9000          // edges + self loops
#define HID  64
#define HEADS 4
#define LL   5
#define GG   64            // B*T graphs
#define RR   64000         // G*N rows
#define NH   64000         // N*HID
#define GATES 192
#define KCH  512
#define NCHUNK 125

#define AGG4_SMEM (NN * 16 * 4)   // 64000 B

// ---------------- device scratch ----------------
__device__ float g_X0[RR * HID];
__device__ float g_X1[RR * HID];
__device__ float g_H [RR * HEADS * HID];
__device__ float g_ls[RR * HEADS];
__device__ float g_ld[RR * HEADS];
__device__ int   g_cnt[NN];
__device__ int   g_off[NN + 1];
__device__ int   g_srcList[EP];
__device__ int   g_eid[EP];
__device__ float g_alpha[GG * HEADS * EP];   // unnormalized softmax weights
__device__ float g_snorm[GG * HEADS * NN];   // 1/sum per (g,h,node)
__device__ float g_GIpart[NCHUNK * GG * GATES];
__device__ float g_GI[GG * GATES];
__device__ float g_hT[BB * HID];

// ---------------- CSR build part A: histogram ----------------
__global__ void __launch_bounds__(1024) k_csr_a(const int* __restrict__ edge_index) {
    __shared__ int scnt[1024];
    int tid = threadIdx.x;
    scnt[tid] = 0;
    __syncthreads();
    for (int e = tid; e < EE; e += 1024)
        atomicAdd(&scnt[edge_index[EE + e]], 1);
    __syncthreads();
    if (tid < NN) g_cnt[tid] = scnt[tid];
}

// ---------------- CSR build part B: scan + scatter + stable sort -------------
__global__ void __launch_bounds__(1024) k_csr_b(const int* __restrict__ edge_index) {
    __shared__ int sscan[1024];
    __shared__ int scur[1024];
    int tid = threadIdx.x;
    int v = (tid < NN) ? (g_cnt[tid] + 1) : 0;   // +1 self loop
    sscan[tid] = v;
    __syncthreads();
    for (int o = 1; o < 1024; o <<= 1) {
        int add = (tid >= o) ? sscan[tid - o] : 0;
        __syncthreads();
        sscan[tid] += add;
        __syncthreads();
    }
    if (tid < NN) {
        g_off[tid + 1] = sscan[tid];
        scur[tid] = (tid == 0) ? 0 : sscan[tid - 1];
    }
    if (tid == 0) g_off[0] = 0;
    __syncthreads();
    for (int e = tid; e < EP; e += 1024) {
        int s, d;
        if (e < EE) { s = edge_index[e]; d = edge_index[EE + e]; }
        else        { s = e - EE;        d = e - EE; }
        int pos = atomicAdd(&scur[d], 1);
        g_srcList[pos] = s;
        g_eid[pos] = e;
    }
    __syncthreads();
    if (tid < NN) {                       // stable order by edge id
        int s0 = g_off[tid], s1 = g_off[tid + 1];
        for (int i = s0 + 1; i < s1; i++) {
            int id = g_eid[i], sv = g_srcList[i];
            int j = i - 1;
            while (j >= s0 && g_eid[j] > id) {
                g_eid[j + 1] = g_eid[j];
                g_srcList[j + 1] = g_srcList[j];
                j--;
            }
            g_eid[j + 1] = id;
            g_srcList[j + 1] = sv;
        }
    }
}

// ---------------- input projection ----------------
__global__ void k_input_fc(const float* __restrict__ x,
                           const float* __restrict__ W_in,
                           const float* __restrict__ b_in) {
    int tid = threadIdx.x;
    int r = blockIdx.x * 4 + (tid >> 6);
    int c = tid & 63;
    float s = b_in[c];
#pragma unroll
    for (int f = 0; f < FIN; f++)
        s += x[r * FIN + f] * W_in[f * HID + c];
    g_X0[r * HID + c] = s;
}

// ---------------- GAT GEMM + fused ls/ld epilogue ----------------------------
__global__ void __launch_bounds__(256) k_gat_gemm(int inBuf, const float* __restrict__ W,
                                                  const float* __restrict__ asrc,
                                                  const float* __restrict__ adst) {
    __shared__ float sm[12288];                 // 48KB, aliased
    float (*As)[64]  = (float(*)[64])sm;        // [64][64]
    float (*Ws)[256] = (float(*)[256])(sm + 4096); // [32][256]
    const float* __restrict__ X = inBuf ? g_X1 : g_X0;
    int rowBase = blockIdx.x * 64;
    int tid = threadIdx.x;

    const float4* X4 = (const float4*)(X + (size_t)rowBase * 64);
#pragma unroll
    for (int q = 0; q < 4; q++) {
        int idx = tid + q * 256;
        int r = idx & 63, k4 = idx >> 6;
        float4 v = X4[r * 16 + k4];
        As[k4 * 4 + 0][r] = v.x;
        As[k4 * 4 + 1][r] = v.y;
        As[k4 * 4 + 2][r] = v.z;
        As[k4 * 4 + 3][r] = v.w;
    }

    int lane = tid & 31, w = tid >> 5;
    int ry2 = lane >> 2, cx2 = lane & 3;
    int cg = w * 4 + cx2;                       // 0..31
    float acc[8][8] = {};
    const float4* W4 = (const float4*)W;

#pragma unroll
    for (int half = 0; half < 2; half++) {
        __syncthreads();
#pragma unroll
        for (int q = 0; q < 8; q++) {
            int idx = tid + q * 256;
            ((float4*)Ws)[idx] = W4[half * 2048 + idx];
        }
        __syncthreads();
#pragma unroll
        for (int kk = 0; kk < 32; kk++) {
            int k = half * 32 + kk;
            float4 a0 = *(const float4*)&As[k][ry2 * 4];
            float4 a1 = *(const float4*)&As[k][32 + ry2 * 4];
            float4 b0 = *(const float4*)&Ws[kk][cg * 4];
            float4 b1 = *(const float4*)&Ws[kk][128 + cg * 4];
            float av[8] = {a0.x, a0.y, a0.z, a0.w, a1.x, a1.y, a1.z, a1.w};
            float bv[8] = {b0.x, b0.y, b0.z, b0.w, b1.x, b1.y, b1.z, b1.w};
#pragma unroll
            for (int i = 0; i < 8; i++)
#pragma unroll
                for (int j = 0; j < 8; j++)
                    acc[i][j] += av[i] * bv[j];
        }
    }
    // store H
#pragma unroll
    for (int i = 0; i < 8; i++) {
        int r = rowBase + ((i < 4) ? (ry2 * 4 + i) : (32 + ry2 * 4 + (i - 4)));
        *(float4*)&g_H[(size_t)r * 256 + cg * 4] =
            make_float4(acc[i][0], acc[i][1], acc[i][2], acc[i][3]);
        *(float4*)&g_H[(size_t)r * 256 + 128 + cg * 4] =
            make_float4(acc[i][4], acc[i][5], acc[i][6], acc[i][7]);
    }

    // ---- fused ls/ld epilogue ----
    __syncthreads();                            // done reading As/Ws
    float (*redls)[4][16] = (float(*)[4][16])sm;          // [64][4][16]
    float (*redld)[4][16] = (float(*)[4][16])(sm + 4096);
    float as_lo[4], as_hi[4], ad_lo[4], ad_hi[4];
#pragma unroll
    for (int j = 0; j < 4; j++) {
        as_lo[j] = asrc[cg * 4 + j];
        as_hi[j] = asrc[128 + cg * 4 + j];
        ad_lo[j] = adst[cg * 4 + j];
        ad_hi[j] = adst[128 + cg * 4 + j];
    }
    int hA = cg >> 4;                           // head of low half (0/1)
    int slot = (w & 3) * 4 + cx2;               // 0..15
#pragma unroll
    for (int i = 0; i < 8; i++) {
        int r = (i < 4) ? (ry2 * 4 + i) : (32 + ry2 * 4 + (i - 4));
        float pls0 = 0, pls1 = 0, pld0 = 0, pld1 = 0;
#pragma unroll
        for (int j = 0; j < 4; j++) {
            pls0 += acc[i][j] * as_lo[j];
            pls1 += acc[i][4 + j] * as_hi[j];
            pld0 += acc[i][j] * ad_lo[j];
            pld1 += acc[i][4 + j] * ad_hi[j];
        }
        redls[r][hA][slot] = pls0;
        redls[r][2 + hA][slot] = pls1;
        redld[r][hA][slot] = pld0;
        redld[r][2 + hA][slot] = pld1;
    }
    __syncthreads();
    {
        int r = tid >> 2, h = tid & 3;
        float s = 0, d = 0;
#pragma unroll
        for (int k = 0; k < 16; k++) { s += redls[r][h][k]; d += redld[r][h][k]; }
        g_ls[(rowBase + r) * 4 + h] = s;
        g_ld[(rowBase + r) * 4 + h] = d;
    }
}

// ---------------- softmax edge weights + normalizer --------------------------
// grid (GG, HEADS); thread-per-node; serial (deterministic) edge sums.
__global__ void __launch_bounds__(512) k_weights() {
    int g = blockIdx.x, h = blockIdx.y;
    size_t gb = (size_t)g * NN;
    float* __restrict__ aw = g_alpha + (size_t)(g * HEADS + h) * EP;
    float* __restrict__ nrm = g_snorm + (size_t)(g * HEADS + h) * NN;
    for (int n = threadIdx.x; n < NN; n += 512) {
        float ldv = g_ld[(gb + n) * HEADS + h];
        int s0 = g_off[n], s1 = g_off[n + 1];
        float sum = 0.f;
        for (int j = s0; j < s1; j++) {
            int s = g_srcList[j];
            float v = g_ls[(gb + s) * HEADS + h] + ldv;
            v = v > 0.f ? v : 0.2f * v;
            float wv = __expf(v);
            aw[j] = wv;
            sum += wv;
        }
        nrm[n] = 1.f / (sum + 1e-16f);
    }
}

// ---------------- GAT aggregate v4: 16-channel smem slice SpMM ---------------
// grid (GG, 16): slice sl -> head h = sl>>2, colBase = h*64 + (sl&3)*16.
// 512 threads; half-warp (16 lanes) per node. Hs = 64KB -> 3 blocks/SM.
__global__ void __launch_bounds__(512) k_gat_agg4() {
    extern __shared__ float Hs[];               // [1000][16]
    int g = blockIdx.x, sl = blockIdx.y;
    int h = sl >> 2;
    int colBase = h * 64 + (sl & 3) * 16;
    int tid = threadIdx.x;
    int lane = tid & 31, w = tid >> 5;
    int half = lane >> 4, ch = lane & 15;
    size_t gb = (size_t)g * NN;

    // Phase A: load H slice (1000 x 4 float4)
    for (int idx = tid; idx < NN * 4; idx += 512) {
        int n = idx >> 2, c4 = idx & 3;
        ((float4*)Hs)[idx] = *(const float4*)&g_H[(gb + n) * 256 + colBase + c4 * 4];
    }
    __syncthreads();

    const float* __restrict__ aw = g_alpha + (size_t)(g * HEADS + h) * EP;
    const float* __restrict__ nrm = g_snorm + (size_t)(g * HEADS + h) * NN;

    // Phase B: half-warp per node SpMM
    for (int n = w * 2 + half; n < NN; n += 32) {
        int s0 = g_off[n], s1 = g_off[n + 1];
        float acc = 0.f;
        int j = s0;
        for (; j + 2 <= s1; j += 2) {
            float a0 = aw[j],      a1 = aw[j + 1];
            int   i0 = g_srcList[j], i1 = g_srcList[j + 1];
            acc += a0 * Hs[i0 * 16 + ch] + a1 * Hs[i1 * 16 + ch];
        }
        if (j < s1)
            acc += aw[j] * Hs[g_srcList[j] * 16 + ch];
        g_H[(gb + n) * 256 + colBase + ch] = acc * nrm[n];   // in-place
    }
}

// ---------------- head mean + bias + elu -> X ----------------
__global__ void k_finish(const float* __restrict__ bg_l, int outBuf) {
    float* __restrict__ Xout = outBuf ? g_X1 : g_X0;
    int tid = threadIdx.x;
    int r = blockIdx.x * 4 + (tid >> 6);
    int c = tid & 63;
    const float* Hr = &g_H[(size_t)r * 256];
    float v = 0.25f * ((Hr[c] + Hr[64 + c]) + (Hr[128 + c] + Hr[192 + c])) + bg_l[c];
    v = v > 0.f ? v : expm1f(v);
    Xout[(size_t)r * 64 + c] = v;
}

// ---------------- GI split-K GEMM -------------------------------------------
__global__ void __launch_bounds__(256) k_gi_gemm(const float* __restrict__ Wih) {
    __shared__ float As[64][33];
    __shared__ float Ws[64][33];
    int kBase = blockIdx.x * KCH;
    int gateBase = blockIdx.y * 64;
    int tid = threadIdx.x;
    int tx = tid & 15, ty = tid >> 4;
    float acc[4][4] = {};
    for (int kt = 0; kt < KCH / 32; kt++) {
        int k0 = kBase + kt * 32;
#pragma unroll
        for (int i = 0; i < 8; i++) {
            int idx = tid + i * 256;
            int r = idx >> 5, kk = idx & 31;
            As[r][kk] = g_X1[r * NH + k0 + kk];
            Ws[r][kk] = Wih[(size_t)(gateBase + r) * NH + k0 + kk];
        }
        __syncthreads();
#pragma unroll
        for (int kk = 0; kk < 32; kk++) {
            float a[4], wv[4];
#pragma unroll
            for (int i = 0; i < 4; i++) a[i] = As[ty * 4 + i][kk];
#pragma unroll
            for (int j = 0; j < 4; j++) wv[j] = Ws[tx * 4 + j][kk];
#pragma unroll
            for (int i = 0; i < 4; i++)
#pragma unroll
                for (int j = 0; j < 4; j++)
                    acc[i][j] += a[i] * wv[j];
        }
        __syncthreads();
    }
#pragma unroll
    for (int i = 0; i < 4; i++)
#pragma unroll
        for (int j = 0; j < 4; j++)
            g_GIpart[(blockIdx.x * GG + ty * 4 + i) * GATES + gateBase + tx * 4 + j] = acc[i][j];
}

__global__ void k_gi_reduce(const float* __restrict__ b_ih) {
    int idx = blockIdx.x * blockDim.x + threadIdx.x;
    int j = idx % GATES;
    float s = b_ih[j];
    for (int kc = 0; kc < NCHUNK; kc++)
        s += g_GIpart[kc * GG * GATES + idx];
    g_GI[idx] = s;
}

// ---------------- GRU recurrence ----------------
__global__ void __launch_bounds__(256) k_gru(const float* __restrict__ Whh,
                                             const float* __restrict__ bhh) {
    __shared__ float h[BB][HID];
    __shared__ float gh[BB][GATES];
    int tid = threadIdx.x;
    h[tid >> 6][tid & 63] = 0.f;
    __syncthreads();
    for (int t = 0; t < TT; t++) {
#pragma unroll
        for (int q = 0; q < 3; q++) {
            int idx = tid + q * 256;
            int b = idx / GATES, j = idx % GATES;
            float s = bhh[j];
#pragma unroll
            for (int c = 0; c < HID; c++)
                s += h[b][c] * Whh[j * HID + c];
            gh[b][j] = s;
        }
        __syncthreads();
        int b = tid >> 6, c = tid & 63;
        int g = b * TT + t;
        float ir = g_GI[g * GATES + c]        + gh[b][c];
        float iz = g_GI[g * GATES + 64 + c]   + gh[b][64 + c];
        float in = g_GI[g * GATES + 128 + c];
        float hn = gh[b][128 + c];
        float r = 1.f / (1.f + expf(-ir));
        float z = 1.f / (1.f + expf(-iz));
        float nn = tanhf(in + r * hn);
        float hnew = (1.f - z) * nn + z * h[b][c];
        __syncthreads();
        h[b][c] = hnew;
        __syncthreads();
    }
    g_hT[tid] = h[tid >> 6][tid & 63];
}

// ---------------- final FC ----------------
__global__ void k_fc(const float* __restrict__ Wfc, const float* __restrict__ bfc,
                     float* __restrict__ out) {
    int b = blockIdx.x;
    int n = blockIdx.y * 256 + threadIdx.x;
    if (n >= NN) return;
    float s = bfc[n];
#pragma unroll
    for (int c = 0; c < HID; c++)
        s += g_hT[b * HID + c] * Wfc[c * NN + n];
    out[b * NN + n] = s;
}

// ---------------- launcher ----------------
extern "C" void kernel_launch(void* const* d_in, const int* in_sizes, int n_in,
                              void* d_out, int out_size) {
    const float* x_seq = (const float*)d_in[0];
    const int*   edge_index = (const int*)d_in[1];
    const float* W_in = (const float*)d_in[3];
    const float* b_in = (const float*)d_in[4];
    const float* Wg   = (const float*)d_in[5];
    const float* a_src= (const float*)d_in[6];
    const float* a_dst= (const float*)d_in[7];
    const float* bg   = (const float*)d_in[8];
    const float* W_ih = (const float*)d_in[9];
    const float* W_hh = (const float*)d_in[10];
    const float* b_ih = (const float*)d_in[11];
    const float* b_hh = (const float*)d_in[12];
    const float* W_fc = (const float*)d_in[13];
    const float* b_fc = (const float*)d_in[14];
    float* out = (float*)d_out;

    cudaFuncSetAttribute(k_gat_agg4,
                         cudaFuncAttributeMaxDynamicSharedMemorySize, AGG4_SMEM);

    // launches 1-3; #4 = first k_gat_gemm (ncu slot)
    k_csr_a<<<1, 1024>>>(edge_index);
    k_csr_b<<<1, 1024>>>(edge_index);
    k_input_fc<<<RR / 4, 256>>>(x_seq, W_in, b_in);

    for (int l = 0; l < LL; l++) {
        int inBuf = l & 1;
        int outBuf = 1 - inBuf;
        k_gat_gemm<<<RR / 64, 256>>>(inBuf, Wg + (size_t)l * HID * 256,
                                     a_src + (size_t)l * HEADS * HID,
                                     a_dst + (size_t)l * HEADS * HID);
        k_weights<<<dim3(GG, HEADS), 512>>>();
        k_gat_agg4<<<dim3(GG, 16), 512, AGG4_SMEM>>>();
        k_finish<<<RR / 4, 256>>>(bg + (size_t)l * HID, outBuf);
    }
    // final features in g_X1

    k_gi_gemm<<<dim3(NCHUNK, 3), 256>>>(W_ih);
    k_gi_reduce<<<(GG * GATES) / 256, 256>>>(b_ih);
    k_gru<<<1, 256>>>(W_hh, b_hh);
    k_fc<<<dim3(BB, 4), 256>>>(W_fc, b_fc, out);
}

// round 6
// speedup vs baseline: 2.4504x; 1.0283x over previous
#include <cuda_runtime.h>
#include <cuda_bf16.h>

// ---------------- problem constants ----------------
#define BB   4
#define TT   16
#define NN   1000
#define FIN  8
#define EE   8000
#define EP   9000          // edges + self loops
#define HID  64
#define HEADS 4
#define LL   5
#define GG   64            // B*T graphs
#define RR   64000         // G*N rows
#define NH   64000         // N*HID
#define GATES 192
#define KCH  512
#define NCHUNK 125

#define AGG4_SMEM (NN * 16 * 4)   // 64000 B

// H layout: slice-major. Column c of row r lives at
//   g_H[(c>>4) * (RR*16) + r*16 + (c&15)]
#define HSLICE (RR * 16)

// ---------------- device scratch ----------------
__device__ float g_X0[RR * HID];
__device__ float g_X1[RR * HID];
__device__ float g_H [16 * HSLICE];
__device__ float g_ls[RR * HEADS];
__device__ float g_ld[RR * HEADS];
__device__ int   g_off[NN + 1];
__device__ int   g_srcList[EP];
__device__ int   g_eid[EP];
__device__ float g_alpha[GG * HEADS * EP];   // NORMALIZED softmax weights
__device__ float g_GIpart[NCHUNK * GG * GATES];
__device__ float g_GI[GG * GATES];
__device__ float g_hT[BB * HID];

// ---------------- CSR build: ONE kernel, one block (deterministic) -----------
__global__ void __launch_bounds__(1024) k_csr_all(const int* __restrict__ edge_index) {
    __shared__ int scnt[1024];
    __shared__ int sscan[1024];
    __shared__ int scur[1024];
    int tid = threadIdx.x;
    scnt[tid] = 0;
    __syncthreads();
    for (int e = tid; e < EE; e += 1024)
        atomicAdd(&scnt[edge_index[EE + e]], 1);
    __syncthreads();
    int v = (tid < NN) ? (scnt[tid] + 1) : 0;    // +1 self loop
    sscan[tid] = v;
    __syncthreads();
    for (int o = 1; o < 1024; o <<= 1) {
        int add = (tid >= o) ? sscan[tid - o] : 0;
        __syncthreads();
        sscan[tid] += add;
        __syncthreads();
    }
    if (tid < NN) {
        g_off[tid + 1] = sscan[tid];
        scur[tid] = (tid == 0) ? 0 : sscan[tid - 1];
    }
    if (tid == 0) g_off[0] = 0;
    __syncthreads();
    for (int e = tid; e < EP; e += 1024) {
        int s, d;
        if (e < EE) { s = edge_index[e]; d = edge_index[EE + e]; }
        else        { s = e - EE;        d = e - EE; }
        int pos = atomicAdd(&scur[d], 1);
        g_srcList[pos] = s;
        g_eid[pos] = e;
    }
    __syncthreads();
    if (tid < NN) {                       // stable order by edge id
        int s0 = g_off[tid], s1 = g_off[tid + 1];
        for (int i = s0 + 1; i < s1; i++) {
            int id = g_eid[i], sv = g_srcList[i];
            int j = i - 1;
            while (j >= s0 && g_eid[j] > id) {
                g_eid[j + 1] = g_eid[j];
                g_srcList[j + 1] = g_srcList[j];
                j--;
            }
            g_eid[j + 1] = id;
            g_srcList[j + 1] = sv;
        }
    }
}

// ---------------- input projection ----------------
__global__ void k_input_fc(const float* __restrict__ x,
                           const float* __restrict__ W_in,
                           const float* __restrict__ b_in) {
    int tid = threadIdx.x;
    int r = blockIdx.x * 4 + (tid >> 6);
    int c = tid & 63;
    float s = b_in[c];
#pragma unroll
    for (int f = 0; f < FIN; f++)
        s += x[r * FIN + f] * W_in[f * HID + c];
    g_X0[r * HID + c] = s;
}

// ---------------- GAT GEMM + fused ls/ld epilogue ----------------------------
__global__ void __launch_bounds__(256) k_gat_gemm(int inBuf, const float* __restrict__ W,
                                                  const float* __restrict__ asrc,
                                                  const float* __restrict__ adst) {
    __shared__ float sm[12288];                 // 48KB, aliased
    float (*As)[64]  = (float(*)[64])sm;        // [64][64]
    float (*Ws)[256] = (float(*)[256])(sm + 4096); // [32][256]
    const float* __restrict__ X = inBuf ? g_X1 : g_X0;
    int rowBase = blockIdx.x * 64;
    int tid = threadIdx.x;

    const float4* X4 = (const float4*)(X + (size_t)rowBase * 64);
#pragma unroll
    for (int q = 0; q < 4; q++) {
        int idx = tid + q * 256;
        int r = idx & 63, k4 = idx >> 6;
        float4 v = X4[r * 16 + k4];
        As[k4 * 4 + 0][r] = v.x;
        As[k4 * 4 + 1][r] = v.y;
        As[k4 * 4 + 2][r] = v.z;
        As[k4 * 4 + 3][r] = v.w;
    }

    int lane = tid & 31, w = tid >> 5;
    int ry2 = lane >> 2, cx2 = lane & 3;
    int cg = w * 4 + cx2;                       // 0..31
    float acc[8][8] = {};
    const float4* W4 = (const float4*)W;

#pragma unroll
    for (int half = 0; half < 2; half++) {
        __syncthreads();
#pragma unroll
        for (int q = 0; q < 8; q++) {
            int idx = tid + q * 256;
            ((float4*)Ws)[idx] = W4[half * 2048 + idx];
        }
        __syncthreads();
#pragma unroll
        for (int kk = 0; kk < 32; kk++) {
            int k = half * 32 + kk;
            float4 a0 = *(const float4*)&As[k][ry2 * 4];
            float4 a1 = *(const float4*)&As[k][32 + ry2 * 4];
            float4 b0 = *(const float4*)&Ws[kk][cg * 4];
            float4 b1 = *(const float4*)&Ws[kk][128 + cg * 4];
            float av[8] = {a0.x, a0.y, a0.z, a0.w, a1.x, a1.y, a1.z, a1.w};
            float bv[8] = {b0.x, b0.y, b0.z, b0.w, b1.x, b1.y, b1.z, b1.w};
#pragma unroll
            for (int i = 0; i < 8; i++)
#pragma unroll
                for (int j = 0; j < 8; j++)
                    acc[i][j] += av[i] * bv[j];
        }
    }
    // store H in slice-major layout: col cLo = cg*4+j -> slice cg>>2, ch (cg&3)*4+j
    {
        int slLo = cg >> 2, slHi = 8 + (cg >> 2);
        int chB = (cg & 3) * 4;
#pragma unroll
        for (int i = 0; i < 8; i++) {
            int r = rowBase + ((i < 4) ? (ry2 * 4 + i) : (32 + ry2 * 4 + (i - 4)));
            *(float4*)&g_H[(size_t)slLo * HSLICE + r * 16 + chB] =
                make_float4(acc[i][0], acc[i][1], acc[i][2], acc[i][3]);
            *(float4*)&g_H[(size_t)slHi * HSLICE + r * 16 + chB] =
                make_float4(acc[i][4], acc[i][5], acc[i][6], acc[i][7]);
        }
    }

    // ---- fused ls/ld epilogue ----
    __syncthreads();                            // done reading As/Ws
    float (*redls)[4][16] = (float(*)[4][16])sm;          // [64][4][16]
    float (*redld)[4][16] = (float(*)[4][16])(sm + 4096);
    float as_lo[4], as_hi[4], ad_lo[4], ad_hi[4];
#pragma unroll
    for (int j = 0; j < 4; j++) {
        as_lo[j] = asrc[cg * 4 + j];
        as_hi[j] = asrc[128 + cg * 4 + j];
        ad_lo[j] = adst[cg * 4 + j];
        ad_hi[j] = adst[128 + cg * 4 + j];
    }
    int hA = cg >> 4;                           // head of low half (0/1)
    int slot = (w & 3) * 4 + cx2;               // 0..15
#pragma unroll
    for (int i = 0; i < 8; i++) {
        int r = (i < 4) ? (ry2 * 4 + i) : (32 + ry2 * 4 + (i - 4));
        float pls0 = 0, pls1 = 0, pld0 = 0, pld1 = 0;
#pragma unroll
        for (int j = 0; j < 4; j++) {
            pls0 += acc[i][j] * as_lo[j];
            pls1 += acc[i][4 + j] * as_hi[j];
            pld0 += acc[i][j] * ad_lo[j];
            pld1 += acc[i][4 + j] * ad_hi[j];
        }
        redls[r][hA][slot] = pls0;
        redls[r][2 + hA][slot] = pls1;
        redld[r][hA][slot] = pld0;
        redld[r][2 + hA][slot] = pld1;
    }
    __syncthreads();
    {
        int r = tid >> 2, h = tid & 3;
        float s = 0, d = 0;
#pragma unroll
        for (int k = 0; k < 16; k++) { s += redls[r][h][k]; d += redld[r][h][k]; }
        g_ls[(rowBase + r) * 4 + h] = s;
        g_ld[(rowBase + r) * 4 + h] = d;
    }
}

// ---------------- softmax edge weights, pre-normalized -----------------------
// grid (GG, HEADS); thread-per-node; serial (deterministic) edge sums.
__global__ void __launch_bounds__(512) k_weights() {
    int g = blockIdx.x, h = blockIdx.y;
    size_t gb = (size_t)g * NN;
    float* __restrict__ aw = g_alpha + (size_t)(g * HEADS + h) * EP;
    for (int n = threadIdx.x; n < NN; n += 512) {
        float ldv = g_ld[(gb + n) * HEADS + h];
        int s0 = g_off[n], s1 = g_off[n + 1];
        float sum = 0.f;
        for (int j = s0; j < s1; j++) {
            int s = g_srcList[j];
            float v = g_ls[(gb + s) * HEADS + h] + ldv;
            v = v > 0.f ? v : 0.2f * v;
            float wv = __expf(v);
            aw[j] = wv;
            sum += wv;
        }
        float inv = 1.f / (sum + 1e-16f);
        for (int j = s0; j < s1; j++)
            aw[j] *= inv;
    }
}

// ---------------- GAT aggregate v5: slice-major, coalesced -------------------
// grid (GG, 16): slice sl, head h = sl>>2. 512 threads; half-warp per node.
__global__ void __launch_bounds__(512) k_gat_agg4() {
    extern __shared__ float Hs[];               // [1000][16]
    int g = blockIdx.x, sl = blockIdx.y;
    int h = sl >> 2;
    int tid = threadIdx.x;
    int lane = tid & 31, w = tid >> 5;
    int half = lane >> 4, ch = lane & 15;
    size_t gb = (size_t)g * NN;
    float* __restrict__ Hsl = g_H + (size_t)sl * HSLICE + gb * 16;

    // Phase A: fully coalesced contiguous 64KB copy
    const float4* src4 = (const float4*)Hsl;
    for (int idx = tid; idx < NN * 4; idx += 512)
        ((float4*)Hs)[idx] = src4[idx];
    __syncthreads();

    const float* __restrict__ aw = g_alpha + (size_t)(g * HEADS + h) * EP;

    // Phase B: half-warp per node SpMM (alpha pre-normalized)
    for (int n = w * 2 + half; n < NN; n += 32) {
        int s0 = g_off[n], s1 = g_off[n + 1];
        float acc = 0.f;
        int j = s0;
        for (; j + 2 <= s1; j += 2) {
            float a0 = aw[j],        a1 = aw[j + 1];
            int   i0 = g_srcList[j], i1 = g_srcList[j + 1];
            acc += a0 * Hs[i0 * 16 + ch] + a1 * Hs[i1 * 16 + ch];
        }
        if (j < s1)
            acc += aw[j] * Hs[g_srcList[j] * 16 + ch];
        Hsl[n * 16 + ch] = acc;                 // in-place, coalesced
    }
}

// ---------------- head mean + bias + elu -> X ----------------
__global__ void k_finish(const float* __restrict__ bg_l, int outBuf) {
    float* __restrict__ Xout = outBuf ? g_X1 : g_X0;
    int tid = threadIdx.x;
    int r = blockIdx.x * 4 + (tid >> 6);
    int c = tid & 63;
    float v = 0.f;
#pragma unroll
    for (int h = 0; h < HEADS; h++) {
        int cc = h * 64 + c;
        v += g_H[(size_t)(cc >> 4) * HSLICE + (size_t)r * 16 + (cc & 15)];
    }
    v = 0.25f * v + bg_l[c];
    v = v > 0.f ? v : expm1f(v);
    Xout[(size_t)r * 64 + c] = v;
}

// ---------------- GI split-K GEMM -------------------------------------------
__global__ void __launch_bounds__(256) k_gi_gemm(const float* __restrict__ Wih) {
    __shared__ float As[64][33];
    __shared__ float Ws[64][33];
    int kBase = blockIdx.x * KCH;
    int gateBase = blockIdx.y * 64;
    int tid = threadIdx.x;
    int tx = tid & 15, ty = tid >> 4;
    float acc[4][4] = {};
    for (int kt = 0; kt < KCH / 32; kt++) {
        int k0 = kBase + kt * 32;
#pragma unroll
        for (int i = 0; i < 8; i++) {
            int idx = tid + i * 256;
            int r = idx >> 5, kk = idx & 31;
            As[r][kk] = g_X1[r * NH + k0 + kk];
            Ws[r][kk] = Wih[(size_t)(gateBase + r) * NH + k0 + kk];
        }
        __syncthreads();
#pragma unroll
        for (int kk = 0; kk < 32; kk++) {
            float a[4], wv[4];
#pragma unroll
            for (int i = 0; i < 4; i++) a[i] = As[ty * 4 + i][kk];
#pragma unroll
            for (int j = 0; j < 4; j++) wv[j] = Ws[tx * 4 + j][kk];
#pragma unroll
            for (int i = 0; i < 4; i++)
#pragma unroll
                for (int j = 0; j < 4; j++)
                    acc[i][j] += a[i] * wv[j];
        }
        __syncthreads();
    }
#pragma unroll
    for (int i = 0; i < 4; i++)
#pragma unroll
        for (int j = 0; j < 4; j++)
            g_GIpart[(blockIdx.x * GG + ty * 4 + i) * GATES + gateBase + tx * 4 + j] = acc[i][j];
}

__global__ void k_gi_reduce(const float* __restrict__ b_ih) {
    int idx = blockIdx.x * blockDim.x + threadIdx.x;
    int j = idx % GATES;
    float s = b_ih[j];
    for (int kc = 0; kc < NCHUNK; kc++)
        s += g_GIpart[kc * GG * GATES + idx];
    g_GI[idx] = s;
}

// ---------------- GRU recurrence ----------------
__global__ void __launch_bounds__(256) k_gru(const float* __restrict__ Whh,
                                             const float* __restrict__ bhh) {
    __shared__ float h[BB][HID];
    __shared__ float gh[BB][GATES];
    int tid = threadIdx.x;
    h[tid >> 6][tid & 63] = 0.f;
    __syncthreads();
    for (int t = 0; t < TT; t++) {
#pragma unroll
        for (int q = 0; q < 3; q++) {
            int idx = tid + q * 256;
            int b = idx / GATES, j = idx % GATES;
            float s = bhh[j];
#pragma unroll
            for (int c = 0; c < HID; c++)
                s += h[b][c] * Whh[j * HID + c];
            gh[b][j] = s;
        }
        __syncthreads();
        int b = tid >> 6, c = tid & 63;
        int g = b * TT + t;
        float ir = g_GI[g * GATES + c]        + gh[b][c];
        float iz = g_GI[g * GATES + 64 + c]   + gh[b][64 + c];
        float in = g_GI[g * GATES + 128 + c];
        float hn = gh[b][128 + c];
        float r = 1.f / (1.f + expf(-ir));
        float z = 1.f / (1.f + expf(-iz));
        float nn = tanhf(in + r * hn);
        float hnew = (1.f - z) * nn + z * h[b][c];
        __syncthreads();
        h[b][c] = hnew;
        __syncthreads();
    }
    g_hT[tid] = h[tid >> 6][tid & 63];
}

// ---------------- final FC ----------------
__global__ void k_fc(const float* __restrict__ Wfc, const float* __restrict__ bfc,
                     float* __restrict__ out) {
    int b = blockIdx.x;
    int n = blockIdx.y * 256 + threadIdx.x;
    if (n >= NN) return;
    float s = bfc[n];
#pragma unroll
    for (int c = 0; c < HID; c++)
        s += g_hT[b * HID + c] * Wfc[c * NN + n];
    out[b * NN + n] = s;
}

// ---------------- launcher ----------------
extern "C" void kernel_launch(void* const* d_in, const int* in_sizes, int n_in,
                              void* d_out, int out_size) {
    const float* x_seq = (const float*)d_in[0];
    const int*   edge_index = (const int*)d_in[1];
    const float* W_in = (const float*)d_in[3];
    const float* b_in = (const float*)d_in[4];
    const float* Wg   = (const float*)d_in[5];
    const float* a_src= (const float*)d_in[6];
    const float* a_dst= (const float*)d_in[7];
    const float* bg   = (const float*)d_in[8];
    const float* W_ih = (const float*)d_in[9];
    const float* W_hh = (const float*)d_in[10];
    const float* b_ih = (const float*)d_in[11];
    const float* b_hh = (const float*)d_in[12];
    const float* W_fc = (const float*)d_in[13];
    const float* b_fc = (const float*)d_in[14];
    float* out = (float*)d_out;

    cudaFuncSetAttribute(k_gat_agg4,
                         cudaFuncAttributeMaxDynamicSharedMemorySize, AGG4_SMEM);

    // launches 1-3; #4 = first k_weights (ncu slot)
    k_csr_all<<<1, 1024>>>(edge_index);
    k_input_fc<<<RR / 4, 256>>>(x_seq, W_in, b_in);

    for (int l = 0; l < LL; l++) {
        int inBuf = l & 1;
        int outBuf = 1 - inBuf;
        k_gat_gemm<<<RR / 64, 256>>>(inBuf, Wg + (size_t)l * HID * 256,
                                     a_src + (size_t)l * HEADS * HID,
                                     a_dst + (size_t)l * HEADS * HID);
        k_weights<<<dim3(GG, HEADS), 512>>>();
        k_gat_agg4<<<dim3(GG, 16), 512, AGG4_SMEM>>>();
        k_finish<<<RR / 4, 256>>>(bg + (size_t)l * HID, outBuf);
    }
    // final features in g_X1

    k_gi_gemm<<<dim3(NCHUNK, 3), 256>>>(W_ih);
    k_gi_reduce<<<(GG * GATES) / 256, 256>>>(b_ih);
    k_gru<<<1, 256>>>(W_hh, b_hh);
    k_fc<<<dim3(BB, 4), 256>>>(W_fc, b_fc, out);
}